// round 16
// baseline (speedup 1.0000x reference)
#include <cuda_runtime.h>
#include <cuda_fp16.h>
#include <stdint.h>
#include <math.h>

#define Nn 4096
#define Hh 500
#define Dd 8
#define NHEADS 5
#define NG 2000
#define KP 512          // padded K per part (halfs)
#define NPG 2048        // padded gates N
#define NPF 512         // padded fc N
#define NPZ 2560        // padded z N
#define NZ 2500

#define BM 128
#define AW 20           // uint32 words per smem row (40 halfs = 80B, conflict-free)
#define SLOT (BM * AW * 4)          // 10240 B per buffer slot
#define NSTAGE 3
#define BREG (NSTAGE * SLOT)
#define SMEMSZ (2 * NSTAGE * SLOT)  // 61440 B -> 3 CTAs/SM

// ---------------- scratch ----------------
__device__ __half g_x16A[(size_t)Nn * KP];
__device__ __half g_x16B[(size_t)Nn * KP];
__device__ __half g_h16A[(size_t)Nn * KP];
__device__ __half g_h16B[(size_t)Nn * KP];
__device__ float  g_c[(size_t)Nn * Hh];
__device__ __half g_xw[(size_t)Dd * Nn * NPG];   // per-layer x@Wih+bias, all 8 steps (134MB)
__device__ __half g_wg[(size_t)NPG * 1024];
__device__ __half g_wfc[(size_t)NPF * 1024];
__device__ __half g_wz[(size_t)NPZ * 512];
__device__ float  g_bpg[NPG];
__device__ float  g_bfc[NPF];
__device__ float  g_z[(size_t)Nn * NZ];
__device__ float  g_el[Nn * NHEADS];
__device__ float  g_er[Nn * NHEADS];

// ---------------- helpers ----------------
__device__ __forceinline__ float sigm(float x) { return 1.f / (1.f + expf(-x)); }
__device__ __forceinline__ uint32_t s2u(const void* p) {
    uint32_t a;
    asm("{ .reg .u64 t; cvta.to.shared.u64 t, %1; cvt.u32.u64 %0, t; }" : "=r"(a) : "l"(p));
    return a;
}
__device__ __forceinline__ void cpa16(uint32_t s, const void* g) {
    asm volatile("cp.async.cg.shared.global [%0], [%1], 16;" :: "r"(s), "l"(g));
}
__device__ __forceinline__ void cpa_commit() {
    asm volatile("cp.async.commit_group;" ::: "memory");
}
template <int N>
__device__ __forceinline__ void cpa_wait() {
    asm volatile("cp.async.wait_group %0;" :: "n"(N) : "memory");
}
__device__ __forceinline__ void ldsm4(uint32_t* r, uint32_t a) {
    asm volatile("ldmatrix.sync.aligned.m8n8.x4.shared.b16 {%0,%1,%2,%3}, [%4];"
        : "=r"(r[0]), "=r"(r[1]), "=r"(r[2]), "=r"(r[3]) : "r"(a));
}
__device__ __forceinline__ void mma16(float c[4], const uint32_t a[4], const uint32_t b[2]) {
    asm volatile(
        "mma.sync.aligned.m16n8k16.row.col.f32.f16.f16.f32 "
        "{%0,%1,%2,%3}, {%4,%5,%6,%7}, {%8,%9}, {%0,%1,%2,%3};"
        : "+f"(c[0]), "+f"(c[1]), "+f"(c[2]), "+f"(c[3])
        : "r"(a[0]), "r"(a[1]), "r"(a[2]), "r"(a[3]), "r"(b[0]), "r"(b[1]));
}

// ---------------- utility kernels ----------------
__global__ void zero_k(float* p, int n) {
    int i = blockIdx.x * blockDim.x + threadIdx.x;
    if (i < n) p[i] = 0.f;
}
__global__ void embed16_k(const int* __restrict__ ids, const float* __restrict__ emb) {
    int i = blockIdx.x * blockDim.x + threadIdx.x;
    if (i < Nn * KP) {
        int n = i >> 9, j = i & 511;
        g_x16A[i] = __float2half(j < Hh ? emb[(size_t)ids[n] * Hh + j] : 0.f);
    }
}
__global__ void build_wg_k(const float* __restrict__ Wih, const float* __restrict__ Whh,
                           const float* __restrict__ bih, const float* __restrict__ bhh) {
    int idx = blockIdx.x * blockDim.x + threadIdx.x;
    if (idx >= NPG * 1024) return;
    int n = idx >> 10, k = idx & 1023;
    float v = 0.f;
    if (n < NG) {
        int gate = n & 3, j = n >> 2, scol = gate * Hh + j;
        if (k < 512) { if (k < Hh) v = Wih[(size_t)k * NG + scol]; }
        else { int kk = k - 512; if (kk < Hh) v = Whh[(size_t)kk * NG + scol]; }
        if (k == 0) g_bpg[n] = bih[scol] + bhh[scol];
    } else if (k == 0) g_bpg[n] = 0.f;
    g_wg[idx] = __float2half(v);
}
__global__ void build_wfc_k(const float* __restrict__ Wself, const float* __restrict__ Wneigh,
                            const float* __restrict__ b) {
    int idx = blockIdx.x * blockDim.x + threadIdx.x;
    if (idx >= NPF * 1024) return;
    int n = idx >> 10, k = idx & 1023;
    float v = 0.f;
    if (n < Hh) {
        if (k < 512) { if (k < Hh) v = Wself[(size_t)k * Hh + n]; }
        else { int kk = k - 512; if (kk < Hh) v = Wneigh[(size_t)kk * Hh + n]; }
        if (k == 0) g_bfc[n] = b[n];
    } else if (k == 0) g_bfc[n] = 0.f;
    g_wfc[idx] = __float2half(v);
}
__global__ void build_wz_k(const float* __restrict__ Wg) {
    int idx = blockIdx.x * blockDim.x + threadIdx.x;
    if (idx >= NPZ * 512) return;
    int n = idx >> 9, k = idx & 511;
    float v = 0.f;
    if (n < NZ && k < Hh) v = Wg[(size_t)k * NZ + n];
    g_wz[idx] = __float2half(v);
}
// t=0 cell: gates = xw[0] (bias included), c_prev = 0.
__global__ void cell0_k(__half* __restrict__ Hout) {
    int i = blockIdx.x * blockDim.x + threadIdx.x;
    if (i >= Nn * Hh) return;
    int n = i / Hh, j = i % Hh;
    const uint2 packed = *reinterpret_cast<const uint2*>(&g_xw[(size_t)n * NPG + 4 * j]);
    __half2 p0 = *reinterpret_cast<const __half2*>(&packed.x);
    __half2 p1 = *reinterpret_cast<const __half2*>(&packed.y);
    float vi = __half2float(__low2half(p0));
    float vg = __half2float(__low2half(p1));
    float vo = __half2float(__high2half(p1));
    float c = sigm(vi) * tanhf(vg);
    g_c[i] = c;
    Hout[(size_t)n * KP + j] = __float2half(sigm(vo) * tanhf(c));
}

// ---------------- shared GEMM core (3-stage ring, 1-ahead prefetch) ----------------
struct GemmCore {
    uint32_t smb;
    int lane, am0, bn0;
    uint32_t aoff, boff;

    __device__ __forceinline__ void init(uint32_t smem_base, int tid) {
        smb = smem_base;
        lane = tid & 31;
        const int warp = tid >> 5;
        am0 = (warp >> 1) * 64;
        bn0 = (warp & 1) * 64;
        aoff = (uint32_t)((lane & 15) * 80 + ((lane >> 4) & 1) * 16);
        boff = (uint32_t)((((lane >> 4) & 1) * 8 + (lane & 7)) * 80 + ((lane >> 3) & 1) * 16);
    }
    __device__ __forceinline__ void stage(int tid, int buf, const __half* asrc, const __half* bsrc) {
        const uint32_t ad = smb + buf * SLOT + tid * 80;
        const uint32_t bd = smb + BREG + buf * SLOT + tid * 80;
#pragma unroll
        for (int q = 0; q < 4; q++) cpa16(ad + q * 16, asrc + q * 8);
#pragma unroll
        for (int q = 0; q < 4; q++) cpa16(bd + q * 16, bsrc + q * 8);
        cpa_commit();
    }
    __device__ __forceinline__ void compute(int buf, float acc[4][8][4]) {
        const uint32_t aS = smb + buf * SLOT;
        const uint32_t bS = smb + BREG + buf * SLOT;
#pragma unroll
        for (int s = 0; s < 2; s++) {
            uint32_t fa[4][4], fb[8][2];
#pragma unroll
            for (int mt = 0; mt < 4; mt++)
                ldsm4(fa[mt], aS + (uint32_t)((am0 + mt * 16) * 80 + s * 32) + aoff);
#pragma unroll
            for (int ntp = 0; ntp < 4; ntp++) {
                uint32_t rr[4];
                ldsm4(rr, bS + (uint32_t)((bn0 + ntp * 16) * 80 + s * 32) + boff);
                fb[2 * ntp][0] = rr[0]; fb[2 * ntp][1] = rr[1];
                fb[2 * ntp + 1][0] = rr[2]; fb[2 * ntp + 1][1] = rr[3];
            }
#pragma unroll
            for (int mt = 0; mt < 4; mt++)
#pragma unroll
                for (int nt = 0; nt < 8; nt++)
                    mma16(acc[mt][nt], fa[mt], fb[nt]);
        }
    }
};

#define GEMM_MAINLOOP(core, tid, ntiles, ASRC, BSRC, acc)                      \
    do {                                                                       \
        (core).stage(tid, 0, ASRC(0), BSRC(0));                                \
        int slot = 0;                                                          \
        for (int tt = 0; tt < (ntiles); tt++) {                                \
            if (tt + 1 < (ntiles)) {                                           \
                int ns = (slot == NSTAGE - 1) ? 0 : slot + 1;                  \
                (core).stage(tid, ns, ASRC(tt + 1), BSRC(tt + 1));             \
                cpa_wait<1>();                                                 \
            } else cpa_wait<0>();                                              \
            __syncthreads();                                                   \
            (core).compute(slot, acc);                                         \
            slot = (slot == NSTAGE - 1) ? 0 : slot + 1;                        \
        }                                                                      \
    } while (0)

#define ACC_INIT(acc)                                                          \
    _Pragma("unroll")                                                          \
    for (int mt = 0; mt < 4; mt++)                                             \
        _Pragma("unroll")                                                      \
        for (int nt = 0; nt < 8; nt++)                                         \
            _Pragma("unroll")                                                  \
            for (int r = 0; r < 4; r++) acc[mt][nt][r] = 0.f;

// ---------------- xw precompute: [x_nbr(t)] @ Wih + bias -> g_xw (all 8 steps) ----------------
__global__ __launch_bounds__(128, 3) void gemm16_xw_k(
    const __half* __restrict__ X, const int* __restrict__ nbr)
{
    extern __shared__ __align__(128) char dyn_smem[];
    const int tid = threadIdx.x;
    const int bm = blockIdx.y * BM;             // 0..32767
    const int bn = blockIdx.x * BM;
    const int g = (tid & 31) >> 2, tig = tid & 3;
    const int t = bm >> 12;                     // timestep
    const int n = (bm + tid) & (Nn - 1);

    GemmCore core;
    core.init(s2u(dyn_smem), tid);

    const __half* a0 = X + (size_t)nbr[n * Dd + t] * KP;
    const __half* wr = g_wg + (size_t)(bn + tid) * 1024;

    float acc[4][8][4];
    ACC_INIT(acc);

    auto ASRC = [&](int tt) { return a0 + tt * 32; };
    auto BSRC = [&](int tt) { return wr + tt * 32; };
    GEMM_MAINLOOP(core, tid, 16, ASRC, BSRC, acc);

#pragma unroll
    for (int mt = 0; mt < 4; mt++) {
        const size_t row0 = bm + core.am0 + mt * 16 + g;
#pragma unroll
        for (int nt = 0; nt < 8; nt++) {
            const int col = bn + core.bn0 + nt * 8 + 2 * tig;
            const float ba = g_bpg[col], bb = g_bpg[col + 1];
            __half2 o0 = __floats2half2_rn(acc[mt][nt][0] + ba, acc[mt][nt][1] + bb);
            __half2 o1 = __floats2half2_rn(acc[mt][nt][2] + ba, acc[mt][nt][3] + bb);
            *reinterpret_cast<__half2*>(&g_xw[row0 * NPG + col]) = o0;
            *reinterpret_cast<__half2*>(&g_xw[(row0 + 8) * NPG + col]) = o1;
        }
    }
}

// ---------------- serial: h@Whh (K=512) + xw[t] + fused LSTM cell ----------------
__global__ __launch_bounds__(128, 3) void gates16_h_k(
    const __half* __restrict__ Hin, const __half* __restrict__ XWt,
    __half* __restrict__ Hout)
{
    extern __shared__ __align__(128) char dyn_smem[];
    const int tid = threadIdx.x;
    const int bm = blockIdx.y * BM;
    const int bn = blockIdx.x * BM;
    const int g = (tid & 31) >> 2, tig = tid & 3;

    GemmCore core;
    core.init(s2u(dyn_smem), tid);

    const __half* a1 = Hin + (size_t)(bm + tid) * KP;
    const __half* wr = g_wg + (size_t)(bn + tid) * 1024 + 512;   // h-part of weights

    float acc[4][8][4];
    ACC_INIT(acc);

    auto ASRC = [&](int tt) { return a1 + tt * 32; };
    auto BSRC = [&](int tt) { return wr + tt * 32; };
    GEMM_MAINLOOP(core, tid, 16, ASRC, BSRC, acc);

    // epilogue: + xw[t] (bias included), then cell. cols interleaved 4j+gate.
#pragma unroll
    for (int mt = 0; mt < 4; mt++) {
        const int row0 = bm + core.am0 + mt * 16 + g;
#pragma unroll
        for (int nt = 0; nt < 8; nt++) {
            const int col = bn + core.bn0 + nt * 8 + 2 * tig;
            const bool ok = col < NG;
            float v0 = 0.f, v1 = 0.f, v2 = 0.f, v3 = 0.f;
            if (ok) {
                __half2 x0 = *reinterpret_cast<const __half2*>(&XWt[(size_t)row0 * NPG + col]);
                __half2 x1 = *reinterpret_cast<const __half2*>(&XWt[(size_t)(row0 + 8) * NPG + col]);
                v0 = acc[mt][nt][0] + __half2float(__low2half(x0));
                v1 = acc[mt][nt][1] + __half2float(__high2half(x0));
                v2 = acc[mt][nt][2] + __half2float(__low2half(x1));
                v3 = acc[mt][nt][3] + __half2float(__high2half(x1));
            }
            float gg0 = __shfl_xor_sync(0xFFFFFFFFu, v0, 1);
            float oo0 = __shfl_xor_sync(0xFFFFFFFFu, v1, 1);
            float gg1 = __shfl_xor_sync(0xFFFFFFFFu, v2, 1);
            float oo1 = __shfl_xor_sync(0xFFFFFFFFu, v3, 1);
            if (ok && (tig & 1) == 0) {
                const int j = col >> 2;
                {
                    float cp = g_c[(size_t)row0 * Hh + j];
                    float c = sigm(v1) * cp + sigm(v0) * tanhf(gg0);
                    g_c[(size_t)row0 * Hh + j] = c;
                    Hout[(size_t)row0 * KP + j] = __float2half(sigm(oo0) * tanhf(c));
                }
                {
                    const int r1 = row0 + 8;
                    float cp = g_c[(size_t)r1 * Hh + j];
                    float c = sigm(v3) * cp + sigm(v2) * tanhf(gg1);
                    g_c[(size_t)r1 * Hh + j] = c;
                    Hout[(size_t)r1 * KP + j] = __float2half(sigm(oo1) * tanhf(c));
                }
            }
        }
    }
}

// ---------------- generic fp16 GEMM (fc / z) ----------------
__global__ __launch_bounds__(128, 3) void gemm16_k(
    const __half* __restrict__ A0, const __half* __restrict__ A1,
    const __half* __restrict__ Wt, int wstride, int ntiles,
    const float* __restrict__ bias, int act,
    __half* __restrict__ out16, float* __restrict__ out32, int ncols)
{
    extern __shared__ __align__(128) char dyn_smem[];
    const int tid = threadIdx.x;
    const int bm = blockIdx.y * BM;
    const int bn = blockIdx.x * BM;
    const int g = (tid & 31) >> 2, tig = tid & 3;

    GemmCore core;
    core.init(s2u(dyn_smem), tid);

    const __half* a0 = A0 + (size_t)(bm + tid) * KP;
    const __half* a1 = A1 ? (A1 + (size_t)(bm + tid) * KP) : nullptr;
    const __half* wr = Wt + (size_t)(bn + tid) * wstride;

    float acc[4][8][4];
    ACC_INIT(acc);

    auto ASRC = [&](int tt) { return (tt < 16) ? (a0 + tt * 32) : (a1 + (tt - 16) * 32); };
    auto BSRC = [&](int tt) { return wr + tt * 32; };
    GEMM_MAINLOOP(core, tid, ntiles, ASRC, BSRC, acc);

#pragma unroll
    for (int mt = 0; mt < 4; mt++) {
        const int row0 = bm + core.am0 + mt * 16 + g;
#pragma unroll
        for (int nt = 0; nt < 8; nt++) {
            const int col = bn + core.bn0 + nt * 8 + 2 * tig;
            if (col < ncols) {
                float ba = 0.f, bb = 0.f;
                if (bias) { ba = bias[col]; bb = bias[col + 1]; }
                float v0 = acc[mt][nt][0] + ba;
                float v1 = acc[mt][nt][1] + bb;
                float v2 = acc[mt][nt][2] + ba;
                float v3 = acc[mt][nt][3] + bb;
                if (act) {
                    v0 = fmaxf(v0, 0.f); v1 = fmaxf(v1, 0.f);
                    v2 = fmaxf(v2, 0.f); v3 = fmaxf(v3, 0.f);
                }
                if (out16) {
                    out16[(size_t)row0 * KP + col] = __float2half(v0);
                    out16[(size_t)row0 * KP + col + 1] = __float2half(v1);
                    out16[(size_t)(row0 + 8) * KP + col] = __float2half(v2);
                    out16[(size_t)(row0 + 8) * KP + col + 1] = __float2half(v3);
                } else {
                    *reinterpret_cast<float2*>(&out32[(size_t)row0 * ncols + col]) = make_float2(v0, v1);
                    *reinterpret_cast<float2*>(&out32[(size_t)(row0 + 8) * ncols + col]) = make_float2(v2, v3);
                }
            }
        }
    }
}

// ---------------- GAT attention scores ----------------
__global__ void gat_scores_k(const float* __restrict__ al, const float* __restrict__ ar) {
    int w = (blockIdx.x * blockDim.x + threadIdx.x) >> 5;
    int lane = threadIdx.x & 31;
    if (w >= Nn * NHEADS) return;
    int n = w / NHEADS, hd = w % NHEADS;
    const float* zr = g_z + (size_t)n * NZ + hd * Hh;
    float sl = 0.f, sr = 0.f;
    for (int c = lane; c < Hh; c += 32) {
        float zv = zr[c];
        sl = fmaf(zv, al[hd * Hh + c], sl);
        sr = fmaf(zv, ar[hd * Hh + c], sr);
    }
#pragma unroll
    for (int o = 16; o; o >>= 1) {
        sl += __shfl_xor_sync(0xFFFFFFFFu, sl, o);
        sr += __shfl_xor_sync(0xFFFFFFFFu, sr, o);
    }
    if (lane == 0) { g_el[w] = sl; g_er[w] = sr; }
}

// ---------------- fused GAT aggregate + relu + head-mean + elu + readout + segsum ----------------
__global__ __launch_bounds__(256) void gat_final_k(
    const int* __restrict__ nbr, const int* __restrict__ gid,
    const float* __restrict__ Wr, const float* __restrict__ br,
    float* __restrict__ out)
{
    int n = blockIdx.x;
    int tid = threadIdx.x;
    __shared__ float alpha[NHEADS][Dd];
    __shared__ int nb[Dd];
    __shared__ float red[256];

    if (tid < Dd) nb[tid] = nbr[n * Dd + tid];
    __syncthreads();

    if (tid < NHEADS * Dd) {
        int hd = tid / Dd, d = tid % Dd;
        float e = g_el[nb[d] * NHEADS + hd] + g_er[n * NHEADS + hd];
        alpha[hd][d] = (e > 0.f) ? e : 0.2f * e;
    }
    __syncthreads();
    if (tid < NHEADS) {
        float mx = -1e30f;
#pragma unroll
        for (int d = 0; d < Dd; d++) mx = fmaxf(mx, alpha[tid][d]);
        float ex[Dd]; float s = 0.f;
#pragma unroll
        for (int d = 0; d < Dd; d++) { ex[d] = expf(alpha[tid][d] - mx); s += ex[d]; }
        float inv = 1.f / s;
#pragma unroll
        for (int d = 0; d < Dd; d++) alpha[tid][d] = ex[d] * inv;
    }
    __syncthreads();

    float accum = 0.f;
    for (int c = tid; c < Hh; c += 256) {
        float mean = 0.f;
#pragma unroll
        for (int hd = 0; hd < NHEADS; hd++) {
            float s = 0.f;
#pragma unroll
            for (int d = 0; d < Dd; d++)
                s = fmaf(alpha[hd][d], g_z[(size_t)nb[d] * NZ + hd * Hh + c], s);
            mean += fmaxf(s, 0.f);
        }
        mean *= (1.f / NHEADS);
        float e = (mean > 0.f) ? mean : (expf(mean) - 1.f);
        accum = fmaf(e, Wr[c], accum);
    }
    red[tid] = accum;
    __syncthreads();
    for (int s = 128; s > 0; s >>= 1) {
        if (tid < s) red[tid] += red[tid + s];
        __syncthreads();
    }
    if (tid == 0) atomicAdd(&out[gid[n]], red[0] + br[0]);
}

// ---------------- launch ----------------
extern "C" void kernel_launch(void* const* d_in, const int* in_sizes, int n_in,
                              void* d_out, int out_size) {
    const int* node_ids  = (const int*)d_in[0];
    const int* neighbors = (const int*)d_in[1];
    const int* graph_ids = (const int*)d_in[2];
    const float* emb = (const float*)d_in[4];
    const float* W[3][7];
    int p = 5;
    for (int l = 0; l < 3; l++)
        for (int q = 0; q < 7; q++) W[l][q] = (const float*)d_in[p++];
    const float* Wg = (const float*)d_in[p++];
    const float* al = (const float*)d_in[p++];
    const float* ar = (const float*)d_in[p++];
    const float* Wr = (const float*)d_in[p++];
    const float* br = (const float*)d_in[p++];
    float* out = (float*)d_out;

    __half *x16A, *x16B, *h16A, *h16B, *wfc, *wz, *xw;
    float *z, *bfc;
    cudaGetSymbolAddress((void**)&x16A, g_x16A);
    cudaGetSymbolAddress((void**)&x16B, g_x16B);
    cudaGetSymbolAddress((void**)&h16A, g_h16A);
    cudaGetSymbolAddress((void**)&h16B, g_h16B);
    cudaGetSymbolAddress((void**)&wfc, g_wfc);
    cudaGetSymbolAddress((void**)&wz, g_wz);
    cudaGetSymbolAddress((void**)&xw, g_xw);
    cudaGetSymbolAddress((void**)&z, g_z);
    cudaGetSymbolAddress((void**)&bfc, g_bfc);

    cudaFuncSetAttribute(gemm16_xw_k, cudaFuncAttributeMaxDynamicSharedMemorySize, SMEMSZ);
    cudaFuncSetAttribute(gates16_h_k, cudaFuncAttributeMaxDynamicSharedMemorySize, SMEMSZ);
    cudaFuncSetAttribute(gemm16_k, cudaFuncAttributeMaxDynamicSharedMemorySize, SMEMSZ);

    const int NHP = Nn * KP;
    zero_k<<<1, 64>>>(out, out_size);
    zero_k<<<(NHP / 2 + 255) / 256, 256>>>((float*)x16B, NHP / 2);
    zero_k<<<(NHP / 2 + 255) / 256, 256>>>((float*)h16A, NHP / 2);
    zero_k<<<(NHP / 2 + 255) / 256, 256>>>((float*)h16B, NHP / 2);
    embed16_k<<<(NHP + 255) / 256, 256>>>(node_ids, emb);
    build_wz_k<<<(NPZ * 512 + 255) / 256, 256>>>(Wg);

    dim3 gXW(NPG / BM, (Dd * Nn) / BM);   // 16 x 256
    dim3 gGates(NPG / BM, Nn / BM);       // 16 x 32
    dim3 gFc(NPF / BM, Nn / BM);          // 4 x 32
    dim3 gZ(NPZ / BM, Nn / BM);           // 20 x 32

    __half* xin = x16A;
    __half* xout = x16B;
    for (int l = 0; l < 3; l++) {
        build_wg_k<<<(NPG * 1024 + 255) / 256, 256>>>(W[l][0], W[l][1], W[l][2], W[l][3]);
        build_wfc_k<<<(NPF * 1024 + 255) / 256, 256>>>(W[l][4], W[l][5], W[l][6]);
        gemm16_xw_k<<<gXW, 128, SMEMSZ>>>(xin, neighbors);
        __half* hin = h16A;
        __half* hout = h16B;
        cell0_k<<<(Nn * Hh + 255) / 256, 256>>>(hin);
        for (int t = 1; t < Dd; t++) {
            gates16_h_k<<<gGates, 128, SMEMSZ>>>(hin, xw + (size_t)t * Nn * NPG, hout);
            __half* tmp = hin; hin = hout; hout = tmp;
        }
        gemm16_k<<<gFc, 128, SMEMSZ>>>(xin, hin, wfc, 1024, 32, bfc, 1, xout, nullptr, Hh);
        __half* tmp = xin; xin = xout; xout = tmp;
    }

    gemm16_k<<<gZ, 128, SMEMSZ>>>(xin, nullptr, wz, 512, 16, nullptr, 0, nullptr, z, NZ);
    gat_scores_k<<<(Nn * NHEADS * 32 + 127) / 128, 128>>>(al, ar);
    gat_final_k<<<Nn, 256>>>(neighbors, graph_ids, Wr, br, out);
}

// round 17
// speedup vs baseline: 1.0546x; 1.0546x over previous
#include <cuda_runtime.h>
#include <cuda_fp16.h>
#include <stdint.h>
#include <math.h>

#define Nn 4096
#define Hh 500
#define Dd 8
#define NHEADS 5
#define NG 2000
#define KP 512          // padded K per part (halfs)
#define NPG 2048        // padded gates N
#define NPF 512         // padded fc N
#define NPZ 2560        // padded z N
#define NZ 2500

#define BM 128
#define AW 20           // uint32 words per smem row (40 halfs = 80B, conflict-free)
#define SLOT (BM * AW * 4)          // 10240 B per buffer slot
#define NSTAGE 3
#define BREG (NSTAGE * SLOT)
#define SMEMSZ (2 * NSTAGE * SLOT)  // 61440 B -> 3 CTAs/SM

// ---------------- scratch ----------------
__device__ __half g_x16A[(size_t)Nn * KP];
__device__ __half g_x16B[(size_t)Nn * KP];
__device__ __half g_h16A[(size_t)Nn * KP];
__device__ __half g_h16B[(size_t)Nn * KP];
__device__ float  g_c[(size_t)Nn * Hh];
__device__ __half g_wg[(size_t)NPG * 1024];
__device__ __half g_wfc[(size_t)NPF * 1024];
__device__ __half g_wz[(size_t)NPZ * 512];
__device__ float  g_bpg[NPG];
__device__ float  g_bfc[NPF];
__device__ float  g_z[(size_t)Nn * NZ];
__device__ float  g_el[Nn * NHEADS];
__device__ float  g_er[Nn * NHEADS];

// ---------------- helpers ----------------
__device__ __forceinline__ float sigm(float x) { return 1.f / (1.f + expf(-x)); }
__device__ __forceinline__ uint32_t s2u(const void* p) {
    uint32_t a;
    asm("{ .reg .u64 t; cvta.to.shared.u64 t, %1; cvt.u32.u64 %0, t; }" : "=r"(a) : "l"(p));
    return a;
}
__device__ __forceinline__ void cpa16(uint32_t s, const void* g) {
    asm volatile("cp.async.cg.shared.global [%0], [%1], 16;" :: "r"(s), "l"(g));
}
__device__ __forceinline__ void cpa_commit() {
    asm volatile("cp.async.commit_group;" ::: "memory");
}
template <int N>
__device__ __forceinline__ void cpa_wait() {
    asm volatile("cp.async.wait_group %0;" :: "n"(N) : "memory");
}
__device__ __forceinline__ void ldsm4(uint32_t* r, uint32_t a) {
    asm volatile("ldmatrix.sync.aligned.m8n8.x4.shared.b16 {%0,%1,%2,%3}, [%4];"
        : "=r"(r[0]), "=r"(r[1]), "=r"(r[2]), "=r"(r[3]) : "r"(a));
}
__device__ __forceinline__ void mma16(float c[4], const uint32_t a[4], const uint32_t b[2]) {
    asm volatile(
        "mma.sync.aligned.m16n8k16.row.col.f32.f16.f16.f32 "
        "{%0,%1,%2,%3}, {%4,%5,%6,%7}, {%8,%9}, {%0,%1,%2,%3};"
        : "+f"(c[0]), "+f"(c[1]), "+f"(c[2]), "+f"(c[3])
        : "r"(a[0]), "r"(a[1]), "r"(a[2]), "r"(a[3]), "r"(b[0]), "r"(b[1]));
}

// ---------------- utility kernels ----------------
__global__ void zero_k(float* p, int n) {
    int i = blockIdx.x * blockDim.x + threadIdx.x;
    if (i < n) p[i] = 0.f;
}
__global__ void embed16_k(const int* __restrict__ ids, const float* __restrict__ emb) {
    int i = blockIdx.x * blockDim.x + threadIdx.x;
    if (i < Nn * KP) {
        int n = i >> 9, j = i & 511;
        g_x16A[i] = __float2half(j < Hh ? emb[(size_t)ids[n] * Hh + j] : 0.f);
    }
}
__global__ void build_wg_k(const float* __restrict__ Wih, const float* __restrict__ Whh,
                           const float* __restrict__ bih, const float* __restrict__ bhh) {
    int idx = blockIdx.x * blockDim.x + threadIdx.x;
    if (idx >= NPG * 1024) return;
    int n = idx >> 10, k = idx & 1023;
    float v = 0.f;
    if (n < NG) {
        int gate = n & 3, j = n >> 2, scol = gate * Hh + j;
        if (k < 512) { if (k < Hh) v = Wih[(size_t)k * NG + scol]; }
        else { int kk = k - 512; if (kk < Hh) v = Whh[(size_t)kk * NG + scol]; }
        if (k == 0) g_bpg[n] = bih[scol] + bhh[scol];
    } else if (k == 0) g_bpg[n] = 0.f;
    g_wg[idx] = __float2half(v);
}
__global__ void build_wfc_k(const float* __restrict__ Wself, const float* __restrict__ Wneigh,
                            const float* __restrict__ b) {
    int idx = blockIdx.x * blockDim.x + threadIdx.x;
    if (idx >= NPF * 1024) return;
    int n = idx >> 10, k = idx & 1023;
    float v = 0.f;
    if (n < Hh) {
        if (k < 512) { if (k < Hh) v = Wself[(size_t)k * Hh + n]; }
        else { int kk = k - 512; if (kk < Hh) v = Wneigh[(size_t)kk * Hh + n]; }
        if (k == 0) g_bfc[n] = b[n];
    } else if (k == 0) g_bfc[n] = 0.f;
    g_wfc[idx] = __float2half(v);
}
__global__ void build_wz_k(const float* __restrict__ Wg) {
    int idx = blockIdx.x * blockDim.x + threadIdx.x;
    if (idx >= NPZ * 512) return;
    int n = idx >> 9, k = idx & 511;
    float v = 0.f;
    if (n < NZ && k < Hh) v = Wg[(size_t)k * NZ + n];
    g_wz[idx] = __float2half(v);
}

// ---------------- shared GEMM core (3-stage ring, 1-ahead prefetch) ----------------
struct GemmCore {
    uint32_t smb;
    int lane, am0, bn0;
    uint32_t aoff, boff;

    __device__ __forceinline__ void init(uint32_t smem_base, int tid) {
        smb = smem_base;
        lane = tid & 31;
        const int warp = tid >> 5;
        am0 = (warp >> 1) * 64;
        bn0 = (warp & 1) * 64;
        aoff = (uint32_t)((lane & 15) * 80 + ((lane >> 4) & 1) * 16);
        boff = (uint32_t)((((lane >> 4) & 1) * 8 + (lane & 7)) * 80 + ((lane >> 3) & 1) * 16);
    }
    __device__ __forceinline__ void stage(int tid, int buf, const __half* asrc, const __half* bsrc) {
        const uint32_t ad = smb + buf * SLOT + tid * 80;
        const uint32_t bd = smb + BREG + buf * SLOT + tid * 80;
#pragma unroll
        for (int q = 0; q < 4; q++) cpa16(ad + q * 16, asrc + q * 8);
#pragma unroll
        for (int q = 0; q < 4; q++) cpa16(bd + q * 16, bsrc + q * 8);
        cpa_commit();
    }
    __device__ __forceinline__ void compute(int buf, float acc[4][8][4]) {
        const uint32_t aS = smb + buf * SLOT;
        const uint32_t bS = smb + BREG + buf * SLOT;
#pragma unroll
        for (int s = 0; s < 2; s++) {
            uint32_t fa[4][4], fb[8][2];
#pragma unroll
            for (int mt = 0; mt < 4; mt++)
                ldsm4(fa[mt], aS + (uint32_t)((am0 + mt * 16) * 80 + s * 32) + aoff);
#pragma unroll
            for (int ntp = 0; ntp < 4; ntp++) {
                uint32_t rr[4];
                ldsm4(rr, bS + (uint32_t)((bn0 + ntp * 16) * 80 + s * 32) + boff);
                fb[2 * ntp][0] = rr[0]; fb[2 * ntp][1] = rr[1];
                fb[2 * ntp + 1][0] = rr[2]; fb[2 * ntp + 1][1] = rr[3];
            }
#pragma unroll
            for (int mt = 0; mt < 4; mt++)
#pragma unroll
                for (int nt = 0; nt < 8; nt++)
                    mma16(acc[mt][nt], fa[mt], fb[nt]);
        }
    }
};

// ring mainloop: stage tile tt+1 into slot (tt+1)%3; one sync per tile.
#define GEMM_MAINLOOP(core, tid, ntiles, ASRC, BSRC, acc)                      \
    do {                                                                       \
        (core).stage(tid, 0, ASRC(0), BSRC(0));                                \
        int slot = 0;                                                          \
        for (int tt = 0; tt < (ntiles); tt++) {                                \
            if (tt + 1 < (ntiles)) {                                           \
                int ns = (slot == NSTAGE - 1) ? 0 : slot + 1;                  \
                (core).stage(tid, ns, ASRC(tt + 1), BSRC(tt + 1));             \
                cpa_wait<1>();                                                 \
            } else cpa_wait<0>();                                              \
            __syncthreads();                                                   \
            (core).compute(slot, acc);                                         \
            slot = (slot == NSTAGE - 1) ? 0 : slot + 1;                        \
        }                                                                      \
    } while (0)

#define ACC_INIT(acc)                                                          \
    _Pragma("unroll")                                                          \
    for (int mt = 0; mt < 4; mt++)                                             \
        _Pragma("unroll")                                                      \
        for (int nt = 0; nt < 8; nt++)                                         \
            _Pragma("unroll")                                                  \
            for (int r = 0; r < 4; r++) acc[mt][nt][r] = 0.f;

// ---------------- gates GEMM (fp16 mma) + fused LSTM cell ----------------
__global__ __launch_bounds__(128, 3) void gates16_cell_k(
    const __half* __restrict__ X, const __half* __restrict__ Hin,
    const int* __restrict__ nbr, int t, int first, __half* __restrict__ Hout)
{
    extern __shared__ __align__(128) char dyn_smem[];
    const int tid = threadIdx.x;
    const int bm = blockIdx.y * BM;
    const int bn = blockIdx.x * BM;
    const int g = (tid & 31) >> 2, tig = tid & 3;

    GemmCore core;
    core.init(s2u(dyn_smem), tid);

    const __half* a0 = X + (size_t)nbr[(bm + tid) * Dd + t] * KP;
    const __half* a1 = Hin + (size_t)(bm + tid) * KP;
    const __half* wr = g_wg + (size_t)(bn + tid) * 1024;
    const int ntiles = first ? 16 : 32;

    float acc[4][8][4];
    ACC_INIT(acc);

    auto ASRC = [&](int tt) { return (tt < 16) ? (a0 + tt * 32) : (a1 + (tt - 16) * 32); };
    auto BSRC = [&](int tt) { return wr + tt * 32; };
    GEMM_MAINLOOP(core, tid, ntiles, ASRC, BSRC, acc);

    // fused LSTM cell epilogue: cols interleaved 4j+gate.
#pragma unroll
    for (int mt = 0; mt < 4; mt++) {
        const int row0 = bm + core.am0 + mt * 16 + g;
#pragma unroll
        for (int nt = 0; nt < 8; nt++) {
            const int col = bn + core.bn0 + nt * 8 + 2 * tig;
            const bool ok = col < NG;
            float v0 = 0.f, v1 = 0.f, v2 = 0.f, v3 = 0.f;
            if (ok) {
                const float2 bi = *reinterpret_cast<const float2*>(&g_bpg[col]);
                v0 = acc[mt][nt][0] + bi.x;
                v1 = acc[mt][nt][1] + bi.y;
                v2 = acc[mt][nt][2] + bi.x;
                v3 = acc[mt][nt][3] + bi.y;
            }
            float gg0 = __shfl_xor_sync(0xFFFFFFFFu, v0, 1);
            float oo0 = __shfl_xor_sync(0xFFFFFFFFu, v1, 1);
            float gg1 = __shfl_xor_sync(0xFFFFFFFFu, v2, 1);
            float oo1 = __shfl_xor_sync(0xFFFFFFFFu, v3, 1);
            if (ok && (tig & 1) == 0) {
                const int j = col >> 2;
                {
                    float cp = first ? 0.f : g_c[(size_t)row0 * Hh + j];
                    float c = sigm(v1) * cp + sigm(v0) * tanhf(gg0);
                    g_c[(size_t)row0 * Hh + j] = c;
                    Hout[(size_t)row0 * KP + j] = __float2half(sigm(oo0) * tanhf(c));
                }
                {
                    const int r1 = row0 + 8;
                    float cp = first ? 0.f : g_c[(size_t)r1 * Hh + j];
                    float c = sigm(v3) * cp + sigm(v2) * tanhf(gg1);
                    g_c[(size_t)r1 * Hh + j] = c;
                    Hout[(size_t)r1 * KP + j] = __float2half(sigm(oo1) * tanhf(c));
                }
            }
        }
    }
}

// ---------------- generic fp16 GEMM (fc / z) ----------------
__global__ __launch_bounds__(128, 3) void gemm16_k(
    const __half* __restrict__ A0, const __half* __restrict__ A1,
    const __half* __restrict__ Wt, int wstride, int ntiles,
    const float* __restrict__ bias, int act,
    __half* __restrict__ out16, float* __restrict__ out32, int ncols)
{
    extern __shared__ __align__(128) char dyn_smem[];
    const int tid = threadIdx.x;
    const int bm = blockIdx.y * BM;
    const int bn = blockIdx.x * BM;
    const int g = (tid & 31) >> 2, tig = tid & 3;

    GemmCore core;
    core.init(s2u(dyn_smem), tid);

    const __half* a0 = A0 + (size_t)(bm + tid) * KP;
    const __half* a1 = A1 ? (A1 + (size_t)(bm + tid) * KP) : nullptr;
    const __half* wr = Wt + (size_t)(bn + tid) * wstride;

    float acc[4][8][4];
    ACC_INIT(acc);

    auto ASRC = [&](int tt) { return (tt < 16) ? (a0 + tt * 32) : (a1 + (tt - 16) * 32); };
    auto BSRC = [&](int tt) { return wr + tt * 32; };
    GEMM_MAINLOOP(core, tid, ntiles, ASRC, BSRC, acc);

#pragma unroll
    for (int mt = 0; mt < 4; mt++) {
        const int row0 = bm + core.am0 + mt * 16 + g;
#pragma unroll
        for (int nt = 0; nt < 8; nt++) {
            const int col = bn + core.bn0 + nt * 8 + 2 * tig;
            if (col < ncols) {
                float ba = 0.f, bb = 0.f;
                if (bias) { ba = bias[col]; bb = bias[col + 1]; }
                float v0 = acc[mt][nt][0] + ba;
                float v1 = acc[mt][nt][1] + bb;
                float v2 = acc[mt][nt][2] + ba;
                float v3 = acc[mt][nt][3] + bb;
                if (act) {
                    v0 = fmaxf(v0, 0.f); v1 = fmaxf(v1, 0.f);
                    v2 = fmaxf(v2, 0.f); v3 = fmaxf(v3, 0.f);
                }
                if (out16) {
                    out16[(size_t)row0 * KP + col] = __float2half(v0);
                    out16[(size_t)row0 * KP + col + 1] = __float2half(v1);
                    out16[(size_t)(row0 + 8) * KP + col] = __float2half(v2);
                    out16[(size_t)(row0 + 8) * KP + col + 1] = __float2half(v3);
                } else {
                    *reinterpret_cast<float2*>(&out32[(size_t)row0 * ncols + col]) = make_float2(v0, v1);
                    *reinterpret_cast<float2*>(&out32[(size_t)(row0 + 8) * ncols + col]) = make_float2(v2, v3);
                }
            }
        }
    }
}

// ---------------- GAT attention scores ----------------
__global__ void gat_scores_k(const float* __restrict__ al, const float* __restrict__ ar) {
    int w = (blockIdx.x * blockDim.x + threadIdx.x) >> 5;
    int lane = threadIdx.x & 31;
    if (w >= Nn * NHEADS) return;
    int n = w / NHEADS, hd = w % NHEADS;
    const float* zr = g_z + (size_t)n * NZ + hd * Hh;
    float sl = 0.f, sr = 0.f;
    for (int c = lane; c < Hh; c += 32) {
        float zv = zr[c];
        sl = fmaf(zv, al[hd * Hh + c], sl);
        sr = fmaf(zv, ar[hd * Hh + c], sr);
    }
#pragma unroll
    for (int o = 16; o; o >>= 1) {
        sl += __shfl_xor_sync(0xFFFFFFFFu, sl, o);
        sr += __shfl_xor_sync(0xFFFFFFFFu, sr, o);
    }
    if (lane == 0) { g_el[w] = sl; g_er[w] = sr; }
}

// ---------------- fused GAT aggregate + relu + head-mean + elu + readout + segsum ----------------
__global__ __launch_bounds__(256) void gat_final_k(
    const int* __restrict__ nbr, const int* __restrict__ gid,
    const float* __restrict__ Wr, const float* __restrict__ br,
    float* __restrict__ out)
{
    int n = blockIdx.x;
    int tid = threadIdx.x;
    __shared__ float alpha[NHEADS][Dd];
    __shared__ int nb[Dd];
    __shared__ float red[256];

    if (tid < Dd) nb[tid] = nbr[n * Dd + tid];
    __syncthreads();

    if (tid < NHEADS * Dd) {
        int hd = tid / Dd, d = tid % Dd;
        float e = g_el[nb[d] * NHEADS + hd] + g_er[n * NHEADS + hd];
        alpha[hd][d] = (e > 0.f) ? e : 0.2f * e;
    }
    __syncthreads();
    if (tid < NHEADS) {
        float mx = -1e30f;
#pragma unroll
        for (int d = 0; d < Dd; d++) mx = fmaxf(mx, alpha[tid][d]);
        float ex[Dd]; float s = 0.f;
#pragma unroll
        for (int d = 0; d < Dd; d++) { ex[d] = expf(alpha[tid][d] - mx); s += ex[d]; }
        float inv = 1.f / s;
#pragma unroll
        for (int d = 0; d < Dd; d++) alpha[tid][d] = ex[d] * inv;
    }
    __syncthreads();

    float accum = 0.f;
    for (int c = tid; c < Hh; c += 256) {
        float mean = 0.f;
#pragma unroll
        for (int hd = 0; hd < NHEADS; hd++) {
            float s = 0.f;
#pragma unroll
            for (int d = 0; d < Dd; d++)
                s = fmaf(alpha[hd][d], g_z[(size_t)nb[d] * NZ + hd * Hh + c], s);
            mean += fmaxf(s, 0.f);
        }
        mean *= (1.f / NHEADS);
        float e = (mean > 0.f) ? mean : (expf(mean) - 1.f);
        accum = fmaf(e, Wr[c], accum);
    }
    red[tid] = accum;
    __syncthreads();
    for (int s = 128; s > 0; s >>= 1) {
        if (tid < s) red[tid] += red[tid + s];
        __syncthreads();
    }
    if (tid == 0) atomicAdd(&out[gid[n]], red[0] + br[0]);
}

// ---------------- launch ----------------
extern "C" void kernel_launch(void* const* d_in, const int* in_sizes, int n_in,
                              void* d_out, int out_size) {
    const int* node_ids  = (const int*)d_in[0];
    const int* neighbors = (const int*)d_in[1];
    const int* graph_ids = (const int*)d_in[2];
    const float* emb = (const float*)d_in[4];
    const float* W[3][7];
    int p = 5;
    for (int l = 0; l < 3; l++)
        for (int q = 0; q < 7; q++) W[l][q] = (const float*)d_in[p++];
    const float* Wg = (const float*)d_in[p++];
    const float* al = (const float*)d_in[p++];
    const float* ar = (const float*)d_in[p++];
    const float* Wr = (const float*)d_in[p++];
    const float* br = (const float*)d_in[p++];
    float* out = (float*)d_out;

    __half *x16A, *x16B, *h16A, *h16B, *wfc, *wz;
    float *z, *bfc;
    cudaGetSymbolAddress((void**)&x16A, g_x16A);
    cudaGetSymbolAddress((void**)&x16B, g_x16B);
    cudaGetSymbolAddress((void**)&h16A, g_h16A);
    cudaGetSymbolAddress((void**)&h16B, g_h16B);
    cudaGetSymbolAddress((void**)&wfc, g_wfc);
    cudaGetSymbolAddress((void**)&wz, g_wz);
    cudaGetSymbolAddress((void**)&z, g_z);
    cudaGetSymbolAddress((void**)&bfc, g_bfc);

    cudaFuncSetAttribute(gates16_cell_k, cudaFuncAttributeMaxDynamicSharedMemorySize, SMEMSZ);
    cudaFuncSetAttribute(gemm16_k, cudaFuncAttributeMaxDynamicSharedMemorySize, SMEMSZ);

    const int NHP = Nn * KP;
    dim3 gGates(NPG / BM, Nn / BM);    // 16 x 32
    dim3 gFc(NPF / BM, Nn / BM);       // 4 x 32
    dim3 gZ(NPZ / BM, Nn / BM);        // 20 x 32

    // Launch order arranged so ncu (-s 5 -c 1) captures launch #6 = gates t=1 (full K).
    zero_k<<<(NHP / 2 + 255) / 256, 256>>>((float*)h16A, NHP / 2);   // 1
    zero_k<<<(NHP / 2 + 255) / 256, 256>>>((float*)h16B, NHP / 2);   // 2
    embed16_k<<<(NHP + 255) / 256, 256>>>(node_ids, emb);            // 3

    __half* xin = x16A;
    __half* xout = x16B;
    for (int l = 0; l < 3; l++) {
        build_wg_k<<<(NPG * 1024 + 255) / 256, 256>>>(W[l][0], W[l][1], W[l][2], W[l][3]);  // 4 (l=0)
        __half* hin = h16A;
        __half* hout = h16B;
        for (int t = 0; t < Dd; t++) {
            // l=0: t=0 is launch 5, t=1 is launch 6 (ncu capture target)
            gates16_cell_k<<<gGates, 128, SMEMSZ>>>(xin, hin, neighbors, t, t == 0 ? 1 : 0, hout);
            __half* tmp = hin; hin = hout; hout = tmp;
        }
        if (l == 0)   // zero x16B pads before fc l0 writes into it (pads stay 0 afterward)
            zero_k<<<(NHP / 2 + 255) / 256, 256>>>((float*)x16B, NHP / 2);
        build_wfc_k<<<(NPF * 1024 + 255) / 256, 256>>>(W[l][4], W[l][5], W[l][6]);
        gemm16_k<<<gFc, 128, SMEMSZ>>>(xin, hin, wfc, 1024, 32, bfc, 1, xout, nullptr, Hh);
        __half* tmp = xin; xin = xout; xout = tmp;
    }

    build_wz_k<<<(NPZ * 512 + 255) / 256, 256>>>(Wg);
    gemm16_k<<<gZ, 128, SMEMSZ>>>(xin, nullptr, wz, 512, 16, nullptr, 0, nullptr, z, NZ);
    zero_k<<<1, 64>>>(out, out_size);
    gat_scores_k<<<(Nn * NHEADS * 32 + 127) / 128, 128>>>(al, ar);
    gat_final_k<<<Nn, 256>>>(neighbors, graph_ids, Wr, br, out);
}